// round 5
// baseline (speedup 1.0000x reference)
#include <cuda_runtime.h>

// CapsuleLayer dynamic routing, fully fused into ONE persistent kernel:
// 3 streaming passes (u_hat recomputed from W; b_ij == u_hat·(v0+..+v_{r-1}))
// + in-kernel reductions/squash, separated by flag-array grid barriers.
// 144 CTAs x 256 threads, 1 CTA/SM (176KB smem) -> all co-resident.

#define BB 32
#define JJ 32
#define II 4608
#define DA 8
#define DD 16
#define CHUNK 32
#define NCHUNK 144
#define OUTSZ (BB * JJ * DD)   // 16384
#define CAP_EPS 1e-7f
#define NSYNC 5
#define VSTRIDE 20             // padded v row (floats): 5j mod 32 -> conflict-free

typedef unsigned long long u64;

__device__ float g_partial[NCHUNK * OUTSZ];        // per-chunk partial s (9.4 MB)
__device__ float g_vsum[OUTSZ];                    // v0, then v0+v1
__device__ volatile unsigned g_flag[NSYNC][NCHUNK];
__device__ unsigned g_exit;

__device__ __forceinline__ u64 pack2(float x, float y) {
    u64 r; asm("mov.b64 %0, {%1, %2};" : "=l"(r) : "f"(x), "f"(y)); return r;
}
__device__ __forceinline__ void unpack2(u64 v, float& x, float& y) {
    asm("mov.b64 {%0, %1}, %2;" : "=f"(x), "=f"(y) : "l"(v));
}
__device__ __forceinline__ u64 ffma2(u64 a, u64 b, u64 c) {
    u64 d; asm("fma.rn.f32x2 %0, %1, %2, %3;" : "=l"(d) : "l"(a), "l"(b), "l"(c)); return d;
}

// ---- grid barrier: per-CTA flag words, no atomic contention ----------------
__device__ __forceinline__ void grid_sync(int s) {
    __syncthreads();
    if (threadIdx.x == 0) {
        __threadfence();                    // publish this CTA's global writes
        g_flag[s][blockIdx.x] = 1u;
    }
    if (threadIdx.x < NCHUNK) {
        while (g_flag[s][threadIdx.x] == 0u) { }
    }
    __syncthreads();
    __threadfence();
}

// ---- W tile staging (transpose to [a][d] per j, float4-XOR swizzle) --------
// global tile for i: Wg4[(sj*II + i)*32 + k*8 + sf]; smem float z'=a*16+d at
// phys = j*128 + ((z'>>2) ^ j)*4 + (z'&3)
__device__ __forceinline__ void stage_load(float4* g, const float4* Wg4,
                                           int sj, int sf, int ig) {
#pragma unroll
    for (int k = 0; k < 4; k++) g[k] = Wg4[(sj * II + ig) * 32 + k * 8 + sf];
}
__device__ __forceinline__ void stage_store(float* slot, const float4* g,
                                            int sj, int sq0, int ssub) {
    float* row = slot + sj * 128;
#pragma unroll
    for (int k = 0; k < 4; k++) {
        row[((sq0 + 0  + k) ^ sj) * 4 + ssub] = g[k].x;
        row[((sq0 + 4  + k) ^ sj) * 4 + ssub] = g[k].y;
        row[((sq0 + 8  + k) ^ sj) * 4 + ssub] = g[k].z;
        row[((sq0 + 12 + k) ^ sj) * 4 + ssub] = g[k].w;
    }
}

// ---- one routing pass over this CTA's 32-i chunk ---------------------------
// sh: W ring (4 x 4096 floats), xsh: x chunk, vsh: padded v (PASS>0)
template <int PASS>
__device__ __forceinline__ void do_pass(float* sh, const float* xsh,
                                        const float* vsh, const float4* Wg4) {
    const int t  = threadIdx.x;
    const int j  = t & 31;          // lane = output capsule
    const int w  = t >> 5;          // warp 0..7
    const int b0 = w * 4;           // 4 batches per warp
    const int i0 = blockIdx.x * CHUNK;
    const int sj   = t >> 3;
    const int sf   = t & 7;
    const int ssub = sf >> 1;
    const int sq0  = (sf & 1) << 4;

    // prologue: fill ring slots 0,1; prefetch i0+2
    float4 g[4];
    stage_load(g, Wg4, sj, sf, i0 + 0);
    stage_store(sh, g, sj, sq0, ssub);
    stage_load(g, Wg4, sj, sf, i0 + 1);
    stage_store(sh + 4096, g, sj, sq0, ssub);
    stage_load(g, Wg4, sj, sf, i0 + 2);
    __syncthreads();

    u64 acc2[4][DD / 2];
#pragma unroll
    for (int bi = 0; bi < 4; bi++)
#pragma unroll
        for (int dp = 0; dp < DD / 2; dp++) acc2[bi][dp] = 0ull;

    auto compute = [&](int il) {
        const ulonglong2* wb = (const ulonglong2*)(sh + ((il & 3) << 12) + j * 128);
        const float* xb = xsh + il * 8;

        u64 u2[4][DD / 2];
        if (PASS > 0) {
#pragma unroll
            for (int bi = 0; bi < 4; bi++)
#pragma unroll
                for (int dp = 0; dp < DD / 2; dp++) u2[bi][dp] = 0ull;
        }

#pragma unroll
        for (int a = 0; a < DA; a++) {
            u64 xx[4];
#pragma unroll
            for (int bi = 0; bi < 4; bi++) {
                float xv = xb[(b0 + bi) * 256 + a];      // broadcast LDS
                xx[bi] = pack2(xv, xv);
            }
#pragma unroll
            for (int d4 = 0; d4 < 4; d4++) {
                ulonglong2 wv = wb[((a << 2) | d4) ^ j]; // conflict-free LDS.128
#pragma unroll
                for (int bi = 0; bi < 4; bi++) {
                    if (PASS == 0) {                     // uniform c folded later
                        acc2[bi][2 * d4]     = ffma2(wv.x, xx[bi], acc2[bi][2 * d4]);
                        acc2[bi][2 * d4 + 1] = ffma2(wv.y, xx[bi], acc2[bi][2 * d4 + 1]);
                    } else {
                        u2[bi][2 * d4]     = ffma2(wv.x, xx[bi], u2[bi][2 * d4]);
                        u2[bi][2 * d4 + 1] = ffma2(wv.y, xx[bi], u2[bi][2 * d4 + 1]);
                    }
                }
            }
        }

        if (PASS > 0) {
#pragma unroll
            for (int bi = 0; bi < 4; bi++) {
                // v from padded shared: 4 LDS.128, conflict-free (stride 5 quads)
                const ulonglong2* vp =
                    (const ulonglong2*)(vsh + ((b0 + bi) * JJ + j) * VSTRIDE);
                u64 lp = 0ull;
#pragma unroll
                for (int k = 0; k < 4; k++) {
                    ulonglong2 vv = vp[k];
                    lp = ffma2(u2[bi][2 * k],     vv.x, lp);
                    lp = ffma2(u2[bi][2 * k + 1], vv.y, lp);
                }
                float lo, hi; unpack2(lp, lo, hi);
                // softmax over j = lanes (logits bounded -> skip max-subtract)
                float e = __expf(lo + hi);
                float z = e;
#pragma unroll
                for (int off = 16; off > 0; off >>= 1)
                    z += __shfl_xor_sync(0xffffffffu, z, off);
                float c = __fdividef(e, z);
                u64 cc = pack2(c, c);
#pragma unroll
                for (int dp = 0; dp < DD / 2; dp++)
                    acc2[bi][dp] = ffma2(cc, u2[bi][dp], acc2[bi][dp]);
            }
        }
    };

    for (int pp = 0; pp < CHUNK / 2; ++pp) {
        const int il0 = 2 * pp;
        compute(il0);
        if (pp + 1 < CHUNK / 2) {
            stage_store(sh + (((il0 + 2) & 3) << 12), g, sj, sq0, ssub);
            stage_load(g, Wg4, sj, sf, i0 + il0 + 3);
        }
        compute(il0 + 1);
        if (pp + 1 < CHUNK / 2) {
            stage_store(sh + (((il0 + 3) & 3) << 12), g, sj, sq0, ssub);
            if (pp + 2 < CHUNK / 2)
                stage_load(g, Wg4, sj, sf, i0 + il0 + 4);
            __syncthreads();
        }
    }

    // per-chunk partials (deterministic two-stage reduction)
#pragma unroll
    for (int bi = 0; bi < 4; bi++) {
        u64* p = (u64*)&g_partial[((blockIdx.x * BB + (b0 + bi)) * JJ + j) * DD];
#pragma unroll
        for (int dp = 0; dp < DD / 2; dp++) p[dp] = acc2[bi][dp];
    }
}

// ---- reduce 144 partials + squash. CTAs 0..127, threads 0..127 -------------
// __ldcg everywhere: partials/vsum are rewritten across phases; L1 is stale.
template <int ROUND>
__device__ __forceinline__ void do_squash(float* __restrict__ out) {
    if (blockIdx.x >= 128 || threadIdx.x >= 128) return;
    const int o = (int)blockIdx.x * 128 + threadIdx.x;   // (b*JJ+j)*DD + d
    const float* p = g_partial + o;
    float s0 = 0.f, s1 = 0.f, s2 = 0.f, s3 = 0.f;
    float s4 = 0.f, s5 = 0.f, s6 = 0.f, s7 = 0.f;
#pragma unroll
    for (int c = 0; c < NCHUNK; c += 8) {
        s0 += __ldcg(p + (c + 0) * OUTSZ);
        s1 += __ldcg(p + (c + 1) * OUTSZ);
        s2 += __ldcg(p + (c + 2) * OUTSZ);
        s3 += __ldcg(p + (c + 3) * OUTSZ);
        s4 += __ldcg(p + (c + 4) * OUTSZ);
        s5 += __ldcg(p + (c + 5) * OUTSZ);
        s6 += __ldcg(p + (c + 6) * OUTSZ);
        s7 += __ldcg(p + (c + 7) * OUTSZ);
    }
    float s = ((s0 + s1) + (s2 + s3)) + ((s4 + s5) + (s6 + s7));
    if (ROUND == 0) s *= 0.03125f;            // uniform c = 1/32 folded here

    float sq = s * s;                          // d-groups of 16 aligned in warp
#pragma unroll
    for (int off = 8; off > 0; off >>= 1)
        sq += __shfl_xor_sync(0xffffffffu, sq, off);

    float v = s * (sq / ((1.0f + sq) * sqrtf(sq + CAP_EPS)));

    if (ROUND == 0)      g_vsum[o] = v;
    else if (ROUND == 1) g_vsum[o] = __ldcg(&g_vsum[o]) + v;
    else                 out[o] = v;
}

// ---------------------------------------------------------------------------
// smem (floats): [0,16384) W ring | [16384,24576) x | [24576,45056) v padded
// ---------------------------------------------------------------------------
__global__ void __launch_bounds__(256, 1)
caps_fused(const float* __restrict__ xg, const float* __restrict__ Wg,
           float* __restrict__ out) {
    extern __shared__ float sh[];
    float* xsh = sh + 16384;
    float* vsh = sh + 24576;
    const float4* Wg4 = (const float4*)Wg;
    const int t = threadIdx.x;
    const int i0 = blockIdx.x * CHUNK;

    // x chunk, loaded once for all 3 passes
    for (int idx = t; idx < 8192; idx += 256) {
        int b = idx >> 8;
        xsh[idx] = xg[b * (II * DA) + i0 * DA + (idx & 255)];
    }
    // (pass prologue's __syncthreads covers xsh visibility)

    auto load_v = [&]() {  // g_vsum -> padded shared
        for (int e = t; e < OUTSZ; e += 256) {
            int bj = e >> 4;
            vsh[bj * VSTRIDE + (e & 15)] = __ldcg(&g_vsum[e]);
        }
        __syncthreads();
    };

    do_pass<0>(sh, xsh, vsh, Wg4);
    grid_sync(0);
    do_squash<0>(out);
    grid_sync(1);
    load_v();
    do_pass<1>(sh, xsh, vsh, Wg4);
    grid_sync(2);
    do_squash<1>(out);
    grid_sync(3);
    load_v();
    do_pass<2>(sh, xsh, vsh, Wg4);
    grid_sync(4);
    do_squash<2>(out);

    // exit protocol: last CTA (all spins provably done) resets barrier state
    __threadfence();
    __shared__ unsigned is_last;
    __syncthreads();
    if (t == 0) is_last = (atomicAdd(&g_exit, 1u) == NCHUNK - 1) ? 1u : 0u;
    __syncthreads();
    if (is_last) {
        volatile unsigned* f = &g_flag[0][0];
        for (int e = t; e < NSYNC * NCHUNK; e += 256) f[e] = 0u;
        if (t == 0) g_exit = 0u;
    }
}

// ---------------------------------------------------------------------------
extern "C" void kernel_launch(void* const* d_in, const int* in_sizes, int n_in,
                              void* d_out, int out_size) {
    (void)in_sizes; (void)n_in; (void)out_size;
    const float* xg = (const float*)d_in[0];   // inputs [32,4608,8]
    const float* Wg = (const float*)d_in[1];   // W      [32,4608,16,8]
    float* out = (float*)d_out;                // [32,32,16]

    const int SMEM = 45056 * 4;  // 176 KB dynamic
    cudaFuncSetAttribute(caps_fused, cudaFuncAttributeMaxDynamicSharedMemorySize, SMEM);
    caps_fused<<<NCHUNK, 256, SMEM>>>(xg, Wg, out);
}